// round 7
// baseline (speedup 1.0000x reference)
#include <cuda_runtime.h>
#include <math.h>

// x: (256, 2048, 25, 2) fp32 -> 6,553,600 float4. Only weights[0] used.
// Joints 0..7 rotate by R=[[c,-s],[s,c]]: ox = x*c + y*s ; oy = -x*s + y*c.
//
// 8 grid-strided segments per thread: every LDG.128/STG.128 is warp-coalesced
// and 8 independent loads are in flight per thread (MLP_p1 = 8).
// n4 = 6,553,600 = 8 * 819,200 ; 819,200 = 3200 blocks * 256 (exact).

__global__ void __launch_bounds__(256)
rigid_rot_gs8(const float4* __restrict__ xin,
              const float*  __restrict__ w,
              float4* __restrict__ out,
              unsigned S,        // stride in float4 = total threads
              unsigned dj)       // (2*S) % 25  : joint-index step per segment
{
    unsigned i = blockIdx.x * 256u + threadIdx.x;

    // Front-batched, fully coalesced streaming loads (8 in flight).
    float4 v0 = __ldcs(&xin[i]);
    float4 v1 = __ldcs(&xin[i +      S]);
    float4 v2 = __ldcs(&xin[i + 2u * S]);
    float4 v3 = __ldcs(&xin[i + 3u * S]);
    float4 v4 = __ldcs(&xin[i + 4u * S]);
    float4 v5 = __ldcs(&xin[i + 5u * S]);
    float4 v6 = __ldcs(&xin[i + 6u * S]);
    float4 v7 = __ldcs(&xin[i + 7u * S]);

    float s, c;
    sincosf(__ldg(w), &s, &c);

    unsigned j = (2u * i) % 25u;   // joint of first pair of segment 0

    float4* vs[8] = {&v0, &v1, &v2, &v3, &v4, &v5, &v6, &v7};

    #pragma unroll
    for (int k = 0; k < 8; ++k) {
        float4& v = *vs[k];

        if (j < 8u) {
            float nx = fmaf(v.x, c, v.y * s);
            float ny = fmaf(v.y, c, -v.x * s);
            v.x = nx; v.y = ny;
        }
        unsigned jn = (j + 1u == 25u) ? 0u : (j + 1u);
        if (jn < 8u) {
            float nx = fmaf(v.z, c, v.w * s);
            float ny = fmaf(v.w, c, -v.z * s);
            v.z = nx; v.w = ny;
        }

        // advance joint index by dj (mod 25) for the next segment
        j += dj;
        if (j >= 25u) j -= 25u;
    }

    __stcs(&out[i],          v0);
    __stcs(&out[i +      S], v1);
    __stcs(&out[i + 2u * S], v2);
    __stcs(&out[i + 3u * S], v3);
    __stcs(&out[i + 4u * S], v4);
    __stcs(&out[i + 5u * S], v5);
    __stcs(&out[i + 6u * S], v6);
    __stcs(&out[i + 7u * S], v7);
}

extern "C" void kernel_launch(void* const* d_in, const int* in_sizes, int n_in,
                              void* d_out, int out_size)
{
    const float4* x = (const float4*)d_in[0];
    const float*  w = (const float*)d_in[1];
    float4* out = (float4*)d_out;

    unsigned n4 = (unsigned)(out_size / 4);   // 6,553,600
    unsigned S  = n4 / 8u;                    // 819,200
    unsigned blocks = S / 256u;               // 3200
    unsigned dj = (unsigned)((2ull * S) % 25ull);

    rigid_rot_gs8<<<blocks, 256>>>(x, w, out, S, dj);
}